// round 11
// baseline (speedup 1.0000x reference)
#include <cuda_runtime.h>
#include <math.h>
#include <stdint.h>

#define B_    4
#define L_    2048
#define HID_  2048
#define H_    16
#define DH_   128
#define QKV_  (3 * HID_)          // 6144
#define PW_   (QKV_ + HID_)       // 8192
#define MTOK_ (B_ * L_)           // 8192
#define EPS_  1e-5f
#define SCALE_ 0.08838834764831845f   // 1/sqrt(128)
#define FULLM 0xffffffffu

// Scratch (allocation-free rule: __device__ globals)
__device__ float g_proj[(size_t)MTOK_ * PW_];    // 256 MB
__device__ float g_attn[(size_t)MTOK_ * HID_];   // 64 MB (tf32-rounded by flash)
__device__ float g_hidtf[(size_t)MTOK_ * HID_];  // 64 MB (tf32-rounded hidden)
__device__ float g_wqtf[(size_t)HID_ * PW_];     // 64 MB (tf32-rounded W_qkvg)
__device__ float g_wotf[(size_t)HID_ * HID_];    // 16 MB (tf32-rounded W_out)

__device__ __forceinline__ uint32_t f2tf(float x) {
    uint32_t u;
    asm("cvt.rna.tf32.f32 %0, %1;" : "=r"(u) : "f"(x));
    return u;
}

__device__ __forceinline__ void mma8(float* c, const uint32_t* a, const uint32_t* b) {
    asm volatile(
        "mma.sync.aligned.m16n8k8.row.col.f32.tf32.tf32.f32 "
        "{%0,%1,%2,%3}, {%4,%5,%6,%7}, {%8,%9}, {%0,%1,%2,%3};\n"
        : "+f"(c[0]), "+f"(c[1]), "+f"(c[2]), "+f"(c[3])
        : "r"(a[0]), "r"(a[1]), "r"(a[2]), "r"(a[3]), "r"(b[0]), "r"(b[1]));
}

__device__ __forceinline__ void cpa16(uint32_t dst, const float* src) {
    asm volatile("cp.async.ca.shared.global [%0], [%1], 16;\n"
                 :: "r"(dst), "l"(src));
}

// ===========================================================================
// Elementwise tf32 pre-round
// ===========================================================================
__global__ __launch_bounds__(256) void round_tf32_k(
    const float4* __restrict__ in, float4* __restrict__ outp, int n4)
{
    const int i = blockIdx.x * 256 + threadIdx.x;
    if (i < n4) {
        float4 v = in[i];
        v.x = __uint_as_float(f2tf(v.x));
        v.y = __uint_as_float(f2tf(v.y));
        v.z = __uint_as_float(f2tf(v.z));
        v.w = __uint_as_float(f2tf(v.w));
        outp[i] = v;
    }
}

// ===========================================================================
// cp.async 3-stage tf32 NN GEMM: C[M,N] = A[M,K]*B[K,N], inputs pre-rounded.
// CTA tile 128x128x32, 8 warps (4M x 2N), warp tile 32x64, 2 CTAs/SM.
// One __syncthreads per k-tile; prefetch distance 2 into a disjoint stage.
// ===========================================================================
#define BM 128
#define BN 128
#define BK 32
#define ASTRf 36    // padded floats per A row (==4 mod 32)
#define BSTRf 136   // padded floats per B row (==8 mod 32)
#define A_STAGE (BM * ASTRf)            // 4608 floats
#define B_STAGE (BK * BSTRf)            // 4352 floats
#define STAGE_F (A_STAGE + B_STAGE)     // 8960 floats
#define GEMM_SMEM (3 * STAGE_F * 4)     // 107520 bytes

__global__ __launch_bounds__(256, 2) void gemm_nn_ca(
    const float* __restrict__ A, int lda,
    const float* __restrict__ B, int ldb,
    float* __restrict__ C, int ldc, int K)
{
    extern __shared__ float smf[];
    const int tid = threadIdx.x;
    const int m0 = blockIdx.y * BM, n0 = blockIdx.x * BN;
    const int warp = tid >> 5, lane = tid & 31;
    const int wm = (warp >> 1) * 32;       // 4 warps along M
    const int wn = (warp & 1) * 64;        // 2 warps along N
    const int lr = lane >> 2, lc = lane & 3;

    // cp.async load mapping: A 128x32 (2 thr/row, 16 floats each),
    //                        B 32x128 (8 thr/row, 16 floats each)
    const int arow = tid >> 1;             // 0..127
    const int acol = (tid & 1) * 16;       // float offset
    const int brow = tid >> 3;             // 0..31
    const int bcol = (tid & 7) * 16;       // float offset

    const float* Ag = A + (size_t)(m0 + arow) * lda + acol;
    const float* Bg = B + (size_t)brow * ldb + n0 + bcol;
    const uint32_t sb = (uint32_t)__cvta_generic_to_shared(smf);

#define LOAD_STAGE(s, kt)                                                     \
    {                                                                         \
        const uint32_t ab = sb + ((s) * STAGE_F + arow * ASTRf + acol) * 4;   \
        const float* ag = Ag + (size_t)(kt) * BK;                             \
        _Pragma("unroll")                                                     \
        for (int i = 0; i < 4; i++) cpa16(ab + i * 16, ag + i * 4);           \
        const uint32_t bb =                                                   \
            sb + ((s) * STAGE_F + A_STAGE + brow * BSTRf + bcol) * 4;         \
        const float* bg = Bg + (size_t)(kt) * BK * ldb;                       \
        _Pragma("unroll")                                                     \
        for (int i = 0; i < 4; i++) cpa16(bb + i * 16, bg + i * 4);           \
        asm volatile("cp.async.commit_group;\n" ::: "memory");                \
    }

    float acc[2][8][4];
#pragma unroll
    for (int mt = 0; mt < 2; mt++)
#pragma unroll
        for (int nt = 0; nt < 8; nt++)
#pragma unroll
            for (int e = 0; e < 4; e++) acc[mt][nt][e] = 0.f;

    const int T = K >> 5;   // >= 2 for all uses
    LOAD_STAGE(0, 0);
    LOAD_STAGE(1, 1);

    int s = 0;   // stage being computed this iteration
    for (int t = 0; t < T; t++) {
        if (t + 1 < T) {
            asm volatile("cp.async.wait_group 1;\n" ::: "memory");
        } else {
            asm volatile("cp.async.wait_group 0;\n" ::: "memory");
        }
        __syncthreads();

        // prefetch k-tile t+2 into the stage not read this or next iteration
        if (t + 2 < T) {
            const int sn = (s + 2 >= 3) ? (s - 1) : (s + 2);
            LOAD_STAGE(sn, t + 2);
        }

        const float* As = smf + s * STAGE_F;
        const float* Bs = As + A_STAGE;
#pragma unroll
        for (int kk = 0; kk < 4; kk++) {
            const int k8 = kk * 8;
            uint32_t af[2][4];
#pragma unroll
            for (int mt = 0; mt < 2; mt++) {
                const int r = wm + mt * 16 + lr;
                af[mt][0] = __float_as_uint(As[r * ASTRf + k8 + lc]);
                af[mt][1] = __float_as_uint(As[(r + 8) * ASTRf + k8 + lc]);
                af[mt][2] = __float_as_uint(As[r * ASTRf + k8 + lc + 4]);
                af[mt][3] = __float_as_uint(As[(r + 8) * ASTRf + k8 + lc + 4]);
            }
            uint32_t bf[8][2];
#pragma unroll
            for (int nt = 0; nt < 8; nt++) {
                const int n = wn + nt * 8 + lr;
                bf[nt][0] = __float_as_uint(Bs[(k8 + lc) * BSTRf + n]);
                bf[nt][1] = __float_as_uint(Bs[(k8 + lc + 4) * BSTRf + n]);
            }
#pragma unroll
            for (int mt = 0; mt < 2; mt++)
#pragma unroll
                for (int nt = 0; nt < 8; nt++)
                    mma8(acc[mt][nt], af[mt], bf[nt]);
        }
        s = (s + 1 >= 3) ? 0 : (s + 1);
    }

#pragma unroll
    for (int mt = 0; mt < 2; mt++)
#pragma unroll
        for (int nt = 0; nt < 8; nt++) {
            const int r = m0 + wm + mt * 16 + lr;
            const int c = n0 + wn + nt * 8 + lc * 2;
            *(float2*)(C + (size_t)r * ldc + c) =
                make_float2(acc[mt][nt][0], acc[mt][nt][1]);
            *(float2*)(C + (size_t)(r + 8) * ldc + c) =
                make_float2(acc[mt][nt][2], acc[mt][nt][3]);
        }
#undef LOAD_STAGE
}

// ===========================================================================
// Flash attention (causal, online softmax) + sigmoid-gate epilogue.
// R4-proven version (LDG + on-the-fly tf32 convert); output tf32-rounded.
// ===========================================================================
#define QSTR 132
#define KSTR 132
#define VSTR 136
#define QSZ (128 * QSTR)
#define KSZ (128 * KSTR)
#define VSZ (128 * VSTR)
#define FLASH_SMEM ((QSZ + KSZ + VSZ) * 4)   // 204800 bytes

__global__ __launch_bounds__(256, 1) void flash_kernel(
    const float* __restrict__ proj, float* __restrict__ attn)
{
    extern __shared__ uint32_t sm[];
    uint32_t* Qs = sm;
    uint32_t* Ks = sm + QSZ;
    uint32_t* Vs = sm + QSZ + KSZ;

    const int it = blockIdx.x, bh = blockIdx.y;
    const int b = bh >> 4, h = bh & 15;
    const size_t base = (size_t)b * L_ * PW_;
    const float* Qp = proj + base + (size_t)h * DH_;
    const float* Kp = proj + base + (size_t)(H_ + h) * DH_;
    const float* Vp = proj + base + (size_t)(2 * H_ + h) * DH_;
    const float* Gp = proj + base + QKV_ + (size_t)h * DH_;
    float* Op = attn + (size_t)b * L_ * HID_ + (size_t)h * DH_;

    const int tid = threadIdx.x, warp = tid >> 5, lane = tid & 31;
    const int lr = lane >> 2, lc = lane & 3;
    const int wm = warp * 16;
    const int i0 = it * 128;

    const int qr = tid >> 5, qq = (tid & 31) * 4;
#pragma unroll
    for (int i = 0; i < 16; i++) {
        const int r = qr + i * 8;
        float4 v = *(const float4*)(Qp + (size_t)(i0 + r) * PW_ + qq);
        uint32_t* d = &Qs[r * QSTR + qq];
        d[0] = f2tf(v.x * SCALE_); d[1] = f2tf(v.y * SCALE_);
        d[2] = f2tf(v.z * SCALE_); d[3] = f2tf(v.w * SCALE_);
    }

    float m0v = -1e30f, m1v = -1e30f, l0 = 0.f, l1 = 0.f;
    float oacc[16][4];
#pragma unroll
    for (int nt = 0; nt < 16; nt++)
#pragma unroll
        for (int e = 0; e < 4; e++) oacc[nt][e] = 0.f;

    const int srcA = (lane & 28) | (lc >> 1);
    const int srcB = srcA + 2;
    const int r0g = i0 + wm + lr, r1g = r0g + 8;

    for (int jt = 0; jt <= it; ++jt) {
        const int j0 = jt * 128;
#pragma unroll
        for (int i = 0; i < 16; i++) {
            const int r = qr + i * 8;
            float4 v = *(const float4*)(Kp + (size_t)(j0 + r) * PW_ + qq);
            uint32_t* d = &Ks[r * KSTR + qq];
            d[0] = f2tf(v.x); d[1] = f2tf(v.y); d[2] = f2tf(v.z); d[3] = f2tf(v.w);
            float4 w = *(const float4*)(Vp + (size_t)(j0 + r) * PW_ + qq);
            uint32_t* e = &Vs[r * VSTR + qq];
            e[0] = f2tf(w.x); e[1] = f2tf(w.y); e[2] = f2tf(w.z); e[3] = f2tf(w.w);
        }
        __syncthreads();

        float sacc[16][4];
#pragma unroll
        for (int nt = 0; nt < 16; nt++)
#pragma unroll
            for (int e = 0; e < 4; e++) sacc[nt][e] = 0.f;

#pragma unroll
        for (int k8 = 0; k8 < 16; k8++) {
            const int kb = k8 * 8;
            uint32_t a[4];
            a[0] = Qs[(wm + lr) * QSTR + kb + lc];
            a[1] = Qs[(wm + lr + 8) * QSTR + kb + lc];
            a[2] = Qs[(wm + lr) * QSTR + kb + lc + 4];
            a[3] = Qs[(wm + lr + 8) * QSTR + kb + lc + 4];
#pragma unroll
            for (int nt = 0; nt < 16; nt++) {
                uint32_t bf[2];
                bf[0] = Ks[(nt * 8 + lr) * KSTR + kb + lc];
                bf[1] = Ks[(nt * 8 + lr) * KSTR + kb + lc + 4];
                mma8(sacc[nt], a, bf);
            }
        }

        if (jt == it) {
#pragma unroll
            for (int nt = 0; nt < 16; nt++) {
                const int c0 = j0 + nt * 8 + 2 * lc;
                if (c0 > r0g)     sacc[nt][0] = -1e30f;
                if (c0 + 1 > r0g) sacc[nt][1] = -1e30f;
                if (c0 > r1g)     sacc[nt][2] = -1e30f;
                if (c0 + 1 > r1g) sacc[nt][3] = -1e30f;
            }
        }

        float tm0 = -1e30f, tm1 = -1e30f;
#pragma unroll
        for (int nt = 0; nt < 16; nt++) {
            tm0 = fmaxf(tm0, fmaxf(sacc[nt][0], sacc[nt][1]));
            tm1 = fmaxf(tm1, fmaxf(sacc[nt][2], sacc[nt][3]));
        }
        tm0 = fmaxf(tm0, __shfl_xor_sync(FULLM, tm0, 1));
        tm0 = fmaxf(tm0, __shfl_xor_sync(FULLM, tm0, 2));
        tm1 = fmaxf(tm1, __shfl_xor_sync(FULLM, tm1, 1));
        tm1 = fmaxf(tm1, __shfl_xor_sync(FULLM, tm1, 2));

        const float mn0 = fmaxf(m0v, tm0), mn1 = fmaxf(m1v, tm1);
        const float sc0 = __expf(m0v - mn0), sc1 = __expf(m1v - mn1);
        m0v = mn0; m1v = mn1;

        float rs0 = 0.f, rs1 = 0.f;
#pragma unroll
        for (int nt = 0; nt < 16; nt++) {
            float p0 = __expf(sacc[nt][0] - mn0);
            float p1 = __expf(sacc[nt][1] - mn0);
            float p2 = __expf(sacc[nt][2] - mn1);
            float p3 = __expf(sacc[nt][3] - mn1);
            rs0 += p0 + p1; rs1 += p2 + p3;
            sacc[nt][0] = __uint_as_float(f2tf(p0));
            sacc[nt][1] = __uint_as_float(f2tf(p1));
            sacc[nt][2] = __uint_as_float(f2tf(p2));
            sacc[nt][3] = __uint_as_float(f2tf(p3));
            oacc[nt][0] *= sc0; oacc[nt][1] *= sc0;
            oacc[nt][2] *= sc1; oacc[nt][3] *= sc1;
        }
        rs0 += __shfl_xor_sync(FULLM, rs0, 1);
        rs0 += __shfl_xor_sync(FULLM, rs0, 2);
        rs1 += __shfl_xor_sync(FULLM, rs1, 1);
        rs1 += __shfl_xor_sync(FULLM, rs1, 2);
        l0 = l0 * sc0 + rs0;
        l1 = l1 * sc1 + rs1;

#pragma unroll
        for (int kk = 0; kk < 16; kk++) {
            float x0 = __shfl_sync(FULLM, sacc[kk][0], srcA);
            float x1 = __shfl_sync(FULLM, sacc[kk][1], srcA);
            float x2 = __shfl_sync(FULLM, sacc[kk][2], srcA);
            float x3 = __shfl_sync(FULLM, sacc[kk][3], srcA);
            float y0 = __shfl_sync(FULLM, sacc[kk][0], srcB);
            float y1 = __shfl_sync(FULLM, sacc[kk][1], srcB);
            float y2 = __shfl_sync(FULLM, sacc[kk][2], srcB);
            float y3 = __shfl_sync(FULLM, sacc[kk][3], srcB);
            const bool odd = lc & 1;
            uint32_t a[4];
            a[0] = __float_as_uint(odd ? x1 : x0);
            a[1] = __float_as_uint(odd ? x3 : x2);
            a[2] = __float_as_uint(odd ? y1 : y0);
            a[3] = __float_as_uint(odd ? y3 : y2);
            const int kb = kk * 8;
#pragma unroll
            for (int nt = 0; nt < 16; nt++) {
                uint32_t bf[2];
                bf[0] = Vs[(kb + lc) * VSTR + nt * 8 + lr];
                bf[1] = Vs[(kb + lc + 4) * VSTR + nt * 8 + lr];
                mma8(oacc[nt], a, bf);
            }
        }
        __syncthreads();
    }

    // epilogue: normalize, sigmoid gate, tf32-round (for the out-GEMM), store
    const float inv0 = 1.f / l0, inv1 = 1.f / l1;
#pragma unroll
    for (int nt = 0; nt < 16; nt++) {
        const int c = nt * 8 + 2 * lc;
        const float2 g0 = *(const float2*)(Gp + (size_t)r0g * PW_ + c);
        const float2 g1 = *(const float2*)(Gp + (size_t)r1g * PW_ + c);
        float o0 = oacc[nt][0] * inv0 * (1.f / (1.f + __expf(-g0.x)));
        float o1 = oacc[nt][1] * inv0 * (1.f / (1.f + __expf(-g0.y)));
        float o2 = oacc[nt][2] * inv1 * (1.f / (1.f + __expf(-g1.x)));
        float o3 = oacc[nt][3] * inv1 * (1.f / (1.f + __expf(-g1.y)));
        *(float2*)(Op + (size_t)r0g * HID_ + c) =
            make_float2(__uint_as_float(f2tf(o0)), __uint_as_float(f2tf(o1)));
        *(float2*)(Op + (size_t)r1g * HID_ + c) =
            make_float2(__uint_as_float(f2tf(o2)), __uint_as_float(f2tf(o3)));
    }
}

// ===========================================================================
// RMSNorm + RoPE in place on q (heads 0..15) and k (heads 16..31) of g_proj.
// ===========================================================================
__global__ __launch_bounds__(256) void norm_rope_kernel(float* __restrict__ proj)
{
    const int warp = blockIdx.x * 8 + (threadIdx.x >> 5);
    const int lane = threadIdx.x & 31;
    const int head2 = warp & 31;
    const int tok = warp >> 5;
    const int pos = tok & (L_ - 1);

    float* x = proj + (size_t)tok * PW_ + (size_t)head2 * DH_;
    float v0 = x[lane];
    float v1 = x[lane + 32];
    float v2 = x[lane + 64];
    float v3 = x[lane + 96];

    float ss = v0 * v0 + v1 * v1 + v2 * v2 + v3 * v3;
#pragma unroll
    for (int o = 16; o; o >>= 1) ss += __shfl_xor_sync(FULLM, ss, o);
    const float r = rsqrtf(ss * (1.0f / DH_) + EPS_);
    v0 *= r; v1 *= r; v2 *= r; v3 *= r;

    const float kf = 9.210340371976184f / 64.0f;
    const float fpos = (float)pos;
    const float a0 = fpos * __expf(-kf * (float)lane);
    const float a1 = fpos * __expf(-kf * (float)(lane + 32));
    float c0, s0, c1, s1;
    sincosf(a0, &s0, &c0);
    sincosf(a1, &s1, &c1);

    x[lane]      = v0 * c0 - v2 * s0;
    x[lane + 64] = v0 * s0 + v2 * c0;
    x[lane + 32] = v1 * c1 - v3 * s1;
    x[lane + 96] = v1 * s1 + v3 * c1;
}

// ===========================================================================
extern "C" void kernel_launch(void* const* d_in, const int* in_sizes, int n_in,
                              void* d_out, int out_size)
{
    const float* hidden = (const float*)d_in[0];   // [B,L,HID]
    const float* Wqkvg  = (const float*)d_in[1];   // [HID, PW]
    const float* Wout   = (const float*)d_in[2];   // [HID, HID]
    float* out = (float*)d_out;                    // [B,L,HID]

    float *proj, *attn, *hidtf, *wqtf, *wotf;
    cudaGetSymbolAddress((void**)&proj,  g_proj);
    cudaGetSymbolAddress((void**)&attn,  g_attn);
    cudaGetSymbolAddress((void**)&hidtf, g_hidtf);
    cudaGetSymbolAddress((void**)&wqtf,  g_wqtf);
    cudaGetSymbolAddress((void**)&wotf,  g_wotf);

    cudaFuncSetAttribute(gemm_nn_ca,
                         cudaFuncAttributeMaxDynamicSharedMemorySize, GEMM_SMEM);
    cudaFuncSetAttribute(flash_kernel,
                         cudaFuncAttributeMaxDynamicSharedMemorySize, FLASH_SMEM);

    // 0) pre-round inputs to tf32 (row-major kept)
    {
        const int n4h = MTOK_ * HID_ / 4;
        round_tf32_k<<<(n4h + 255) / 256, 256>>>((const float4*)hidden,
                                                 (float4*)hidtf, n4h);
        const int n4q = HID_ * PW_ / 4;
        round_tf32_k<<<(n4q + 255) / 256, 256>>>((const float4*)Wqkvg,
                                                 (float4*)wqtf, n4q);
        const int n4o = HID_ * HID_ / 4;
        round_tf32_k<<<(n4o + 255) / 256, 256>>>((const float4*)Wout,
                                                 (float4*)wotf, n4o);
    }

    // 1) proj = hidden @ W_qkvg
    gemm_nn_ca<<<dim3(PW_ / BN, MTOK_ / BM), 256, GEMM_SMEM>>>(
        hidtf, HID_, wqtf, PW_, proj, PW_, HID_);

    // 2) RMSNorm + RoPE on q,k
    norm_rope_kernel<<<(MTOK_ * 2 * H_) / 8, 256>>>(proj);

    // 3) fused flash attention + gate (tf32-rounds attn in epilogue)
    flash_kernel<<<dim3(L_ / 128, B_ * H_), 256, FLASH_SMEM>>>(proj, attn);

    // 4) out = attn @ W_out
    gemm_nn_ca<<<dim3(HID_ / BN, MTOK_ / BM), 256, GEMM_SMEM>>>(
        attn, HID_, wotf, HID_, out, HID_, HID_);
}

// round 13
// speedup vs baseline: 1.4434x; 1.4434x over previous
#include <cuda_runtime.h>
#include <math.h>
#include <stdint.h>

#define B_    4
#define L_    2048
#define HID_  2048
#define H_    16
#define DH_   128
#define QKV_  (3 * HID_)          // 6144
#define PW_   (QKV_ + HID_)       // 8192
#define MTOK_ (B_ * L_)           // 8192
#define EPS_  1e-5f
#define SCALE_ 0.08838834764831845f   // 1/sqrt(128)
#define FULLM 0xffffffffu

// Scratch (allocation-free rule: __device__ globals)
__device__ float g_proj[(size_t)MTOK_ * PW_];    // 256 MB
__device__ float g_attn[(size_t)MTOK_ * HID_];   // 64 MB (tf32-rounded by flash)
__device__ float g_hidtf[(size_t)MTOK_ * HID_];  // 64 MB (tf32-rounded hidden)
__device__ float g_wqtf[(size_t)HID_ * PW_];     // 64 MB (tf32-rounded W_qkvg)
__device__ float g_wotf[(size_t)HID_ * HID_];    // 16 MB (tf32-rounded W_out)

__device__ __forceinline__ uint32_t f2tf(float x) {
    uint32_t u;
    asm("cvt.rna.tf32.f32 %0, %1;" : "=r"(u) : "f"(x));
    return u;
}

__device__ __forceinline__ void mma8(float* c, const uint32_t* a, const uint32_t* b) {
    asm volatile(
        "mma.sync.aligned.m16n8k8.row.col.f32.tf32.tf32.f32 "
        "{%0,%1,%2,%3}, {%4,%5,%6,%7}, {%8,%9}, {%0,%1,%2,%3};\n"
        : "+f"(c[0]), "+f"(c[1]), "+f"(c[2]), "+f"(c[3])
        : "r"(a[0]), "r"(a[1]), "r"(a[2]), "r"(a[3]), "r"(b[0]), "r"(b[1]));
}

// ===========================================================================
// Elementwise tf32 pre-round
// ===========================================================================
__global__ __launch_bounds__(256) void round_tf32_k(
    const float4* __restrict__ in, float4* __restrict__ outp, int n4)
{
    const int i = blockIdx.x * 256 + threadIdx.x;
    if (i < n4) {
        float4 v = in[i];
        v.x = __uint_as_float(f2tf(v.x));
        v.y = __uint_as_float(f2tf(v.y));
        v.z = __uint_as_float(f2tf(v.z));
        v.w = __uint_as_float(f2tf(v.w));
        outp[i] = v;
    }
}

// ===========================================================================
// tf32 NN GEMM, 128 threads/CTA, tile 128x128x32, warp tile 64x64,
// G2R->R2S double buffer with interleaved A/B staging, 2 CTAs/SM.
// Inputs pre-rounded tf32 (R2S is a plain copy).
// ===========================================================================
#define BM 128
#define BN 128
#define BK 32
#define ASTR 36                    // ==4 mod 32
#define BSTR 136                   // ==8 mod 32
#define A_ST (BM * ASTR)           // 4608 floats
#define B_ST (BK * BSTR)           // 4352 floats
#define STF  (A_ST + B_ST)         // 8960 floats
#define GEMM_SMEM (2 * STF * 4)    // 71680 bytes

__global__ __launch_bounds__(128, 2) void gemm_nn(
    const float* __restrict__ A, int lda,
    const float* __restrict__ B, int ldb,
    float* __restrict__ C, int ldc, int K)
{
    extern __shared__ float smf[];
    const int tid = threadIdx.x;
    const int m0 = blockIdx.y * BM, n0 = blockIdx.x * BN;
    const int warp = tid >> 5, lane = tid & 31;
    const int wm = (warp >> 1) * 64;     // 2 warps along M
    const int wn = (warp & 1) * 64;      // 2 warps along N
    const int lr = lane >> 2, lc = lane & 3;

    // load mapping (A and B share it): r8 = 0..15, c8 = 0,4,..,28
    const int r8 = tid >> 3;
    const int c8 = (tid & 7) * 4;

    const float* Ag = A + (size_t)(m0 + r8) * lda + c8;    // rows r8+h*16, h=0..7
    const float* Bg = B + (size_t)r8 * ldb + n0 + c8;      // rows r8+h*16, h=0..1

    float4 st[8];

#define G2R_A(kt)                                                            \
    {                                                                        \
        const float* ag = Ag + (size_t)(kt) * BK;                            \
        _Pragma("unroll")                                                    \
        for (int h = 0; h < 8; h++)                                          \
            st[h] = *(const float4*)(ag + (size_t)(h * 16) * lda);           \
    }
#define R2S_A(pp)                                                            \
    {                                                                        \
        float* as = smf + (pp) * STF;                                        \
        _Pragma("unroll")                                                    \
        for (int h = 0; h < 8; h++)                                          \
            *(float4*)(as + (r8 + h * 16) * ASTR + c8) = st[h];              \
    }
#define G2R_B(kt)                                                            \
    {                                                                        \
        const float* bg = Bg + (size_t)(kt) * BK * ldb;                      \
        _Pragma("unroll")                                                    \
        for (int h = 0; h < 2; h++)                                          \
            _Pragma("unroll")                                                \
            for (int j = 0; j < 4; j++)                                      \
                st[h * 4 + j] =                                              \
                    *(const float4*)(bg + (size_t)(h * 16) * ldb + j * 32);  \
    }
#define R2S_B(pp)                                                            \
    {                                                                        \
        float* bs = smf + (pp) * STF + A_ST;                                 \
        _Pragma("unroll")                                                    \
        for (int h = 0; h < 2; h++)                                          \
            _Pragma("unroll")                                                \
            for (int j = 0; j < 4; j++)                                      \
                *(float4*)(bs + (r8 + h * 16) * BSTR + c8 + j * 32) =        \
                    st[h * 4 + j];                                           \
    }

    float acc[4][8][4];
#pragma unroll
    for (int mt = 0; mt < 4; mt++)
#pragma unroll
        for (int nt = 0; nt < 8; nt++)
#pragma unroll
            for (int e = 0; e < 4; e++) acc[mt][nt][e] = 0.f;

#define COMP(pp, k8)                                                         \
    {                                                                        \
        const float* As_ = smf + (pp) * STF;                                 \
        const float* Bs_ = As_ + A_ST;                                       \
        uint32_t af[4][4];                                                   \
        _Pragma("unroll")                                                    \
        for (int mt = 0; mt < 4; mt++) {                                     \
            const int r = wm + mt * 16 + lr;                                 \
            af[mt][0] = __float_as_uint(As_[r * ASTR + (k8) + lc]);          \
            af[mt][1] = __float_as_uint(As_[(r + 8) * ASTR + (k8) + lc]);    \
            af[mt][2] = __float_as_uint(As_[r * ASTR + (k8) + lc + 4]);      \
            af[mt][3] = __float_as_uint(As_[(r + 8) * ASTR + (k8) + lc + 4]);\
        }                                                                    \
        uint32_t bf[8][2];                                                   \
        _Pragma("unroll")                                                    \
        for (int nt = 0; nt < 8; nt++) {                                     \
            const int n = wn + nt * 8 + lr;                                  \
            bf[nt][0] = __float_as_uint(Bs_[((k8) + lc) * BSTR + n]);        \
            bf[nt][1] = __float_as_uint(Bs_[((k8) + lc + 4) * BSTR + n]);    \
        }                                                                    \
        _Pragma("unroll")                                                    \
        for (int mt = 0; mt < 4; mt++)                                       \
            _Pragma("unroll")                                                \
            for (int nt = 0; nt < 8; nt++)                                   \
                mma8(acc[mt][nt], af[mt], bf[nt]);                           \
    }

    // prologue: fill stage 0
    G2R_A(0); R2S_A(0);
    G2R_B(0); R2S_B(0);
    __syncthreads();

    const int T = K >> 5;
    for (int t = 0; t < T; t++) {
        const int p = t & 1;
        const bool nx = (t + 1 < T);
        if (nx) G2R_A(t + 1);
        COMP(p, 0); COMP(p, 8);
        if (nx) { R2S_A(p ^ 1); G2R_B(t + 1); }
        COMP(p, 16); COMP(p, 24);
        if (nx) R2S_B(p ^ 1);
        __syncthreads();
    }

#pragma unroll
    for (int mt = 0; mt < 4; mt++)
#pragma unroll
        for (int nt = 0; nt < 8; nt++) {
            const int r = m0 + wm + mt * 16 + lr;
            const int c = n0 + wn + nt * 8 + lc * 2;
            *(float2*)(C + (size_t)r * ldc + c) =
                make_float2(acc[mt][nt][0], acc[mt][nt][1]);
            *(float2*)(C + (size_t)(r + 8) * ldc + c) =
                make_float2(acc[mt][nt][2], acc[mt][nt][3]);
        }
#undef G2R_A
#undef R2S_A
#undef G2R_B
#undef R2S_B
#undef COMP
}

// ===========================================================================
// Flash attention (causal, online softmax) + sigmoid-gate epilogue.
// R4-proven version; output tf32-rounded for the out-GEMM.
// ===========================================================================
#define QSTR 132
#define KSTR 132
#define VSTR 136
#define QSZ (128 * QSTR)
#define KSZ (128 * KSTR)
#define VSZ (128 * VSTR)
#define FLASH_SMEM ((QSZ + KSZ + VSZ) * 4)   // 204800 bytes

__global__ __launch_bounds__(256, 1) void flash_kernel(
    const float* __restrict__ proj, float* __restrict__ attn)
{
    extern __shared__ uint32_t sm[];
    uint32_t* Qs = sm;
    uint32_t* Ks = sm + QSZ;
    uint32_t* Vs = sm + QSZ + KSZ;

    const int it = blockIdx.x, bh = blockIdx.y;
    const int b = bh >> 4, h = bh & 15;
    const size_t base = (size_t)b * L_ * PW_;
    const float* Qp = proj + base + (size_t)h * DH_;
    const float* Kp = proj + base + (size_t)(H_ + h) * DH_;
    const float* Vp = proj + base + (size_t)(2 * H_ + h) * DH_;
    const float* Gp = proj + base + QKV_ + (size_t)h * DH_;
    float* Op = attn + (size_t)b * L_ * HID_ + (size_t)h * DH_;

    const int tid = threadIdx.x, warp = tid >> 5, lane = tid & 31;
    const int lr = lane >> 2, lc = lane & 3;
    const int wm = warp * 16;
    const int i0 = it * 128;

    const int qr = tid >> 5, qq = (tid & 31) * 4;
#pragma unroll
    for (int i = 0; i < 16; i++) {
        const int r = qr + i * 8;
        float4 v = *(const float4*)(Qp + (size_t)(i0 + r) * PW_ + qq);
        uint32_t* d = &Qs[r * QSTR + qq];
        d[0] = f2tf(v.x * SCALE_); d[1] = f2tf(v.y * SCALE_);
        d[2] = f2tf(v.z * SCALE_); d[3] = f2tf(v.w * SCALE_);
    }

    float m0v = -1e30f, m1v = -1e30f, l0 = 0.f, l1 = 0.f;
    float oacc[16][4];
#pragma unroll
    for (int nt = 0; nt < 16; nt++)
#pragma unroll
        for (int e = 0; e < 4; e++) oacc[nt][e] = 0.f;

    const int srcA = (lane & 28) | (lc >> 1);
    const int srcB = srcA + 2;
    const int r0g = i0 + wm + lr, r1g = r0g + 8;

    for (int jt = 0; jt <= it; ++jt) {
        const int j0 = jt * 128;
#pragma unroll
        for (int i = 0; i < 16; i++) {
            const int r = qr + i * 8;
            float4 v = *(const float4*)(Kp + (size_t)(j0 + r) * PW_ + qq);
            uint32_t* d = &Ks[r * KSTR + qq];
            d[0] = f2tf(v.x); d[1] = f2tf(v.y); d[2] = f2tf(v.z); d[3] = f2tf(v.w);
            float4 w = *(const float4*)(Vp + (size_t)(j0 + r) * PW_ + qq);
            uint32_t* e = &Vs[r * VSTR + qq];
            e[0] = f2tf(w.x); e[1] = f2tf(w.y); e[2] = f2tf(w.z); e[3] = f2tf(w.w);
        }
        __syncthreads();

        float sacc[16][4];
#pragma unroll
        for (int nt = 0; nt < 16; nt++)
#pragma unroll
            for (int e = 0; e < 4; e++) sacc[nt][e] = 0.f;

#pragma unroll
        for (int k8 = 0; k8 < 16; k8++) {
            const int kb = k8 * 8;
            uint32_t a[4];
            a[0] = Qs[(wm + lr) * QSTR + kb + lc];
            a[1] = Qs[(wm + lr + 8) * QSTR + kb + lc];
            a[2] = Qs[(wm + lr) * QSTR + kb + lc + 4];
            a[3] = Qs[(wm + lr + 8) * QSTR + kb + lc + 4];
#pragma unroll
            for (int nt = 0; nt < 16; nt++) {
                uint32_t bf[2];
                bf[0] = Ks[(nt * 8 + lr) * KSTR + kb + lc];
                bf[1] = Ks[(nt * 8 + lr) * KSTR + kb + lc + 4];
                mma8(sacc[nt], a, bf);
            }
        }

        if (jt == it) {
#pragma unroll
            for (int nt = 0; nt < 16; nt++) {
                const int c0 = j0 + nt * 8 + 2 * lc;
                if (c0 > r0g)     sacc[nt][0] = -1e30f;
                if (c0 + 1 > r0g) sacc[nt][1] = -1e30f;
                if (c0 > r1g)     sacc[nt][2] = -1e30f;
                if (c0 + 1 > r1g) sacc[nt][3] = -1e30f;
            }
        }

        float tm0 = -1e30f, tm1 = -1e30f;
#pragma unroll
        for (int nt = 0; nt < 16; nt++) {
            tm0 = fmaxf(tm0, fmaxf(sacc[nt][0], sacc[nt][1]));
            tm1 = fmaxf(tm1, fmaxf(sacc[nt][2], sacc[nt][3]));
        }
        tm0 = fmaxf(tm0, __shfl_xor_sync(FULLM, tm0, 1));
        tm0 = fmaxf(tm0, __shfl_xor_sync(FULLM, tm0, 2));
        tm1 = fmaxf(tm1, __shfl_xor_sync(FULLM, tm1, 1));
        tm1 = fmaxf(tm1, __shfl_xor_sync(FULLM, tm1, 2));

        const float mn0 = fmaxf(m0v, tm0), mn1 = fmaxf(m1v, tm1);
        const float sc0 = __expf(m0v - mn0), sc1 = __expf(m1v - mn1);
        m0v = mn0; m1v = mn1;

        float rs0 = 0.f, rs1 = 0.f;
#pragma unroll
        for (int nt = 0; nt < 16; nt++) {
            float p0 = __expf(sacc[nt][0] - mn0);
            float p1 = __expf(sacc[nt][1] - mn0);
            float p2 = __expf(sacc[nt][2] - mn1);
            float p3 = __expf(sacc[nt][3] - mn1);
            rs0 += p0 + p1; rs1 += p2 + p3;
            sacc[nt][0] = __uint_as_float(f2tf(p0));
            sacc[nt][1] = __uint_as_float(f2tf(p1));
            sacc[nt][2] = __uint_as_float(f2tf(p2));
            sacc[nt][3] = __uint_as_float(f2tf(p3));
            oacc[nt][0] *= sc0; oacc[nt][1] *= sc0;
            oacc[nt][2] *= sc1; oacc[nt][3] *= sc1;
        }
        rs0 += __shfl_xor_sync(FULLM, rs0, 1);
        rs0 += __shfl_xor_sync(FULLM, rs0, 2);
        rs1 += __shfl_xor_sync(FULLM, rs1, 1);
        rs1 += __shfl_xor_sync(FULLM, rs1, 2);
        l0 = l0 * sc0 + rs0;
        l1 = l1 * sc1 + rs1;

#pragma unroll
        for (int kk = 0; kk < 16; kk++) {
            float x0 = __shfl_sync(FULLM, sacc[kk][0], srcA);
            float x1 = __shfl_sync(FULLM, sacc[kk][1], srcA);
            float x2 = __shfl_sync(FULLM, sacc[kk][2], srcA);
            float x3 = __shfl_sync(FULLM, sacc[kk][3], srcA);
            float y0 = __shfl_sync(FULLM, sacc[kk][0], srcB);
            float y1 = __shfl_sync(FULLM, sacc[kk][1], srcB);
            float y2 = __shfl_sync(FULLM, sacc[kk][2], srcB);
            float y3 = __shfl_sync(FULLM, sacc[kk][3], srcB);
            const bool odd = lc & 1;
            uint32_t a[4];
            a[0] = __float_as_uint(odd ? x1 : x0);
            a[1] = __float_as_uint(odd ? x3 : x2);
            a[2] = __float_as_uint(odd ? y1 : y0);
            a[3] = __float_as_uint(odd ? y3 : y2);
            const int kb = kk * 8;
#pragma unroll
            for (int nt = 0; nt < 16; nt++) {
                uint32_t bf[2];
                bf[0] = Vs[(kb + lc) * VSTR + nt * 8 + lr];
                bf[1] = Vs[(kb + lc + 4) * VSTR + nt * 8 + lr];
                mma8(oacc[nt], a, bf);
            }
        }
        __syncthreads();
    }

    const float inv0 = 1.f / l0, inv1 = 1.f / l1;
#pragma unroll
    for (int nt = 0; nt < 16; nt++) {
        const int c = nt * 8 + 2 * lc;
        const float2 g0 = *(const float2*)(Gp + (size_t)r0g * PW_ + c);
        const float2 g1 = *(const float2*)(Gp + (size_t)r1g * PW_ + c);
        float o0 = oacc[nt][0] * inv0 * (1.f / (1.f + __expf(-g0.x)));
        float o1 = oacc[nt][1] * inv0 * (1.f / (1.f + __expf(-g0.y)));
        float o2 = oacc[nt][2] * inv1 * (1.f / (1.f + __expf(-g1.x)));
        float o3 = oacc[nt][3] * inv1 * (1.f / (1.f + __expf(-g1.y)));
        *(float2*)(Op + (size_t)r0g * HID_ + c) =
            make_float2(__uint_as_float(f2tf(o0)), __uint_as_float(f2tf(o1)));
        *(float2*)(Op + (size_t)r1g * HID_ + c) =
            make_float2(__uint_as_float(f2tf(o2)), __uint_as_float(f2tf(o3)));
    }
}

// ===========================================================================
// RMSNorm + RoPE in place on q (heads 0..15) and k (heads 16..31) of g_proj.
// ===========================================================================
__global__ __launch_bounds__(256) void norm_rope_kernel(float* __restrict__ proj)
{
    const int warp = blockIdx.x * 8 + (threadIdx.x >> 5);
    const int lane = threadIdx.x & 31;
    const int head2 = warp & 31;
    const int tok = warp >> 5;
    const int pos = tok & (L_ - 1);

    float* x = proj + (size_t)tok * PW_ + (size_t)head2 * DH_;
    float v0 = x[lane];
    float v1 = x[lane + 32];
    float v2 = x[lane + 64];
    float v3 = x[lane + 96];

    float ss = v0 * v0 + v1 * v1 + v2 * v2 + v3 * v3;
#pragma unroll
    for (int o = 16; o; o >>= 1) ss += __shfl_xor_sync(FULLM, ss, o);
    const float r = rsqrtf(ss * (1.0f / DH_) + EPS_);
    v0 *= r; v1 *= r; v2 *= r; v3 *= r;

    const float kf = 9.210340371976184f / 64.0f;
    const float fpos = (float)pos;
    const float a0 = fpos * __expf(-kf * (float)lane);
    const float a1 = fpos * __expf(-kf * (float)(lane + 32));
    float c0, s0, c1, s1;
    sincosf(a0, &s0, &c0);
    sincosf(a1, &s1, &c1);

    x[lane]      = v0 * c0 - v2 * s0;
    x[lane + 64] = v0 * s0 + v2 * c0;
    x[lane + 32] = v1 * c1 - v3 * s1;
    x[lane + 96] = v1 * s1 + v3 * c1;
}

// ===========================================================================
extern "C" void kernel_launch(void* const* d_in, const int* in_sizes, int n_in,
                              void* d_out, int out_size)
{
    const float* hidden = (const float*)d_in[0];   // [B,L,HID]
    const float* Wqkvg  = (const float*)d_in[1];   // [HID, PW]
    const float* Wout   = (const float*)d_in[2];   // [HID, HID]
    float* out = (float*)d_out;                    // [B,L,HID]

    float *proj, *attn, *hidtf, *wqtf, *wotf;
    cudaGetSymbolAddress((void**)&proj,  g_proj);
    cudaGetSymbolAddress((void**)&attn,  g_attn);
    cudaGetSymbolAddress((void**)&hidtf, g_hidtf);
    cudaGetSymbolAddress((void**)&wqtf,  g_wqtf);
    cudaGetSymbolAddress((void**)&wotf,  g_wotf);

    cudaFuncSetAttribute(gemm_nn,
                         cudaFuncAttributeMaxDynamicSharedMemorySize, GEMM_SMEM);
    cudaFuncSetAttribute(flash_kernel,
                         cudaFuncAttributeMaxDynamicSharedMemorySize, FLASH_SMEM);

    // 0) pre-round inputs to tf32
    {
        const int n4h = MTOK_ * HID_ / 4;
        round_tf32_k<<<(n4h + 255) / 256, 256>>>((const float4*)hidden,
                                                 (float4*)hidtf, n4h);
        const int n4q = HID_ * PW_ / 4;
        round_tf32_k<<<(n4q + 255) / 256, 256>>>((const float4*)Wqkvg,
                                                 (float4*)wqtf, n4q);
        const int n4o = HID_ * HID_ / 4;
        round_tf32_k<<<(n4o + 255) / 256, 256>>>((const float4*)Wout,
                                                 (float4*)wotf, n4o);
    }

    // 1) proj = hidden @ W_qkvg
    gemm_nn<<<dim3(PW_ / BN, MTOK_ / BM), 128, GEMM_SMEM>>>(
        hidtf, HID_, wqtf, PW_, proj, PW_, HID_);

    // 2) RMSNorm + RoPE on q,k
    norm_rope_kernel<<<(MTOK_ * 2 * H_) / 8, 256>>>(proj);

    // 3) fused flash attention + gate (tf32-rounds attn in epilogue)
    flash_kernel<<<dim3(L_ / 128, B_ * H_), 256, FLASH_SMEM>>>(proj, attn);

    // 4) out = attn @ W_out
    gemm_nn<<<dim3(HID_ / BN, MTOK_ / BM), 128, GEMM_SMEM>>>(
        attn, HID_, wotf, HID_, out, HID_, HID_);
}